// round 1
// baseline (speedup 1.0000x reference)
#include <cuda_runtime.h>
#include <cstdint>

#define NN 100000
#define NE 1600000
#define D 128
#define PITCH 132

// Scratch (no allocations allowed)
__device__ float g_neigh[(size_t)NN * D];   // segment sums
__device__ float g_deg[NN];                 // degrees
__device__ int   g_fmt;                     // 1 = int32 indices, 0 = int64

// ---------------------------------------------------------------------------
// Detect whether src/dst are int32 or int64 (JAX default disables x64, so the
// reference's "int64" may actually be int32). For int64 little-endian, every
// odd 32-bit word is a zero high-word (values < 1e5). For int32, odd words are
// random dst/src values in [0,1e5) — 256 consecutive zeros is impossible.
// Deterministic each call.
// ---------------------------------------------------------------------------
__global__ void detect_fmt_kernel(const int* __restrict__ src32) {
    __shared__ int flag;
    if (threadIdx.x == 0) flag = 0;
    __syncthreads();
    if (src32[2 * threadIdx.x + 1] != 0) atomicOr(&flag, 1);
    __syncthreads();
    if (threadIdx.x == 0) g_fmt = flag ? 1 : 0;
}

// ---------------------------------------------------------------------------
// Zero the scratch buffers (d_out is poisoned; scratch must be zeroed per call)
// ---------------------------------------------------------------------------
__global__ void zero_kernel() {
    const int NV = NN * D / 4;       // 3,200,000 float4 for neigh
    const int ND = NN / 4;           // 25,000 float4 for deg
    int idx = blockIdx.x * blockDim.x + threadIdx.x;
    float4 z = make_float4(0.f, 0.f, 0.f, 0.f);
    if (idx < NV) {
        reinterpret_cast<float4*>(g_neigh)[idx] = z;
    } else if (idx < NV + ND) {
        reinterpret_cast<float4*>(g_deg)[idx - NV] = z;
    }
}

// ---------------------------------------------------------------------------
// Edge scatter: one warp per edge. Each lane handles a float4 (128 floats =
// 32 lanes x 4). Gather h[src] coalesced, vector-reduce into g_neigh[dst].
// h and g_neigh both fit in L2, so this is L2-atomic bound; v4 reductions cut
// the atomic op count 4x vs scalar atomicAdd.
// ---------------------------------------------------------------------------
__global__ void __launch_bounds__(256) scatter_kernel(
    const float* __restrict__ h,
    const int* __restrict__ src32,
    const int* __restrict__ dst32,
    int n_edges)
{
    int gw = (blockIdx.x * 256 + threadIdx.x) >> 5;
    if (gw >= n_edges) return;
    int lane = threadIdx.x & 31;

    int s, d;
    if (g_fmt) { s = src32[gw];     d = dst32[gw];     }
    else       { s = src32[2 * gw]; d = dst32[2 * gw]; }

    float4 v = reinterpret_cast<const float4*>(h + (size_t)s * D)[lane];
    float* p = g_neigh + (size_t)d * D + lane * 4;
    asm volatile("red.global.add.v4.f32 [%0], {%1, %2, %3, %4};"
                 :: "l"(p), "f"(v.x), "f"(v.y), "f"(v.z), "f"(v.w)
                 : "memory");
    if (lane == 0) atomicAdd(&g_deg[d], 1.0f);
}

// ---------------------------------------------------------------------------
// Fused GEMM: out = h @ Ws^T + (neigh/deg) @ Wn^T + b
// 256 threads/block, 64 nodes/block. W transposed into smem (pitch 132 ->
// conflict-free 16B column loads). Each thread: 2 nodes x 16 cols, fp32
// accumulation via packed fma.rn.f32x2 (full-rate fp32 on sm_103a).
// ---------------------------------------------------------------------------
__device__ __forceinline__ unsigned long long fma2(
    unsigned long long a, unsigned long long b, unsigned long long c)
{
    unsigned long long d;
    asm("fma.rn.f32x2 %0, %1, %2, %3;" : "=l"(d) : "l"(a), "l"(b), "l"(c));
    return d;
}

__device__ __forceinline__ unsigned long long dup_f32(float a) {
    unsigned long long d;
    asm("mov.b64 %0, {%1, %1};" : "=l"(d) : "f"(a));
    return d;
}

__global__ void __launch_bounds__(256) sage_gemm_kernel(
    const float* __restrict__ h,
    const float* __restrict__ Wself,
    const float* __restrict__ Wneigh,
    const float* __restrict__ bias,
    float* __restrict__ out,
    int n_nodes)
{
    extern __shared__ float smem[];
    float* Wst = smem;                    // [128][PITCH] Wself transposed (k-major)
    float* Wnt = Wst + 128 * PITCH;       // [128][PITCH] Wneigh transposed
    float* hs  = Wnt + 128 * PITCH;       // [64][PITCH]
    float* hns = hs  + 64  * PITCH;       // [64][PITCH]

    const int tid = threadIdx.x;
    const int nodeBase = blockIdx.x * 64;

    // Stage transposed weights (coalesced global reads, scattered smem writes)
    for (int idx = tid; idx < 128 * 128; idx += 256) {
        int j = idx >> 7, k = idx & 127;
        Wst[k * PITCH + j] = Wself[idx];
        Wnt[k * PITCH + j] = Wneigh[idx];
    }

    // Stage h and mean-neighbor tiles
    for (int idx = tid; idx < 64 * 32; idx += 256) {
        int ln = idx >> 5, q = idx & 31;
        int node = nodeBase + ln;
        float4 hv = make_float4(0.f, 0.f, 0.f, 0.f);
        float4 nv = hv;
        float invd = 0.f;
        if (node < n_nodes) {
            hv = reinterpret_cast<const float4*>(h + (size_t)node * D)[q];
            nv = reinterpret_cast<const float4*>(g_neigh + (size_t)node * D)[q];
            invd = 1.0f / fmaxf(g_deg[node], 1.0f);
        }
        *reinterpret_cast<float4*>(hs + ln * PITCH + q * 4) = hv;
        nv.x *= invd; nv.y *= invd; nv.z *= invd; nv.w *= invd;
        *reinterpret_cast<float4*>(hns + ln * PITCH + q * 4) = nv;
    }
    __syncthreads();

    const int ln0 = (tid >> 3) << 1;       // nodes ln0, ln0+1
    const int col = (tid & 7) * 16;        // 16 output columns

    unsigned long long acc0[8], acc1[8];
    #pragma unroll
    for (int q = 0; q < 8; q++) {
        unsigned long long bb = *reinterpret_cast<const unsigned long long*>(bias + col + 2 * q);
        acc0[q] = bb;
        acc1[q] = bb;
    }

    const float* hr0 = hs  + ln0 * PITCH;
    const float* hr1 = hs  + (ln0 + 1) * PITCH;
    const float* nr0 = hns + ln0 * PITCH;
    const float* nr1 = hns + (ln0 + 1) * PITCH;

    #pragma unroll 4
    for (int k = 0; k < 128; k++) {
        unsigned long long a0 = dup_f32(hr0[k]);
        unsigned long long a1 = dup_f32(hr1[k]);
        unsigned long long c0 = dup_f32(nr0[k]);
        unsigned long long c1 = dup_f32(nr1[k]);
        const ulonglong2* wsp = reinterpret_cast<const ulonglong2*>(Wst + k * PITCH + col);
        const ulonglong2* wnp = reinterpret_cast<const ulonglong2*>(Wnt + k * PITCH + col);
        #pragma unroll
        for (int q = 0; q < 4; q++) {
            ulonglong2 ws = wsp[q];
            ulonglong2 wn = wnp[q];
            acc0[2 * q]     = fma2(a0, ws.x, acc0[2 * q]);
            acc0[2 * q + 1] = fma2(a0, ws.y, acc0[2 * q + 1]);
            acc1[2 * q]     = fma2(a1, ws.x, acc1[2 * q]);
            acc1[2 * q + 1] = fma2(a1, ws.y, acc1[2 * q + 1]);
            acc0[2 * q]     = fma2(c0, wn.x, acc0[2 * q]);
            acc0[2 * q + 1] = fma2(c0, wn.y, acc0[2 * q + 1]);
            acc1[2 * q]     = fma2(c1, wn.x, acc1[2 * q]);
            acc1[2 * q + 1] = fma2(c1, wn.y, acc1[2 * q + 1]);
        }
    }

    int node0 = nodeBase + ln0;
    int node1 = node0 + 1;
    if (node0 < n_nodes) {
        unsigned long long* o = reinterpret_cast<unsigned long long*>(out + (size_t)node0 * D + col);
        #pragma unroll
        for (int q = 0; q < 8; q++) o[q] = acc0[q];
    }
    if (node1 < n_nodes) {
        unsigned long long* o = reinterpret_cast<unsigned long long*>(out + (size_t)node1 * D + col);
        #pragma unroll
        for (int q = 0; q < 8; q++) o[q] = acc1[q];
    }
}

// ---------------------------------------------------------------------------
extern "C" void kernel_launch(void* const* d_in, const int* in_sizes, int n_in,
                              void* d_out, int out_size)
{
    const float* h      = (const float*)d_in[0];
    const int*   src32  = (const int*)d_in[1];
    const int*   dst32  = (const int*)d_in[2];
    const float* Wself  = (const float*)d_in[3];
    const float* Wneigh = (const float*)d_in[4];
    const float* bias   = (const float*)d_in[5];
    float*       out    = (float*)d_out;

    const int n_nodes = in_sizes[0] / D;   // 100000
    const int n_edges = in_sizes[1];       // 1600000 (element count, dtype-independent)

    static int smem_set = 0;
    const int smem_bytes = (2 * 128 * PITCH + 2 * 64 * PITCH) * sizeof(float); // 202752
    if (!smem_set) {
        cudaFuncSetAttribute(sage_gemm_kernel,
                             cudaFuncAttributeMaxDynamicSharedMemorySize, smem_bytes);
        smem_set = 1;
    }

    detect_fmt_kernel<<<1, 256>>>(src32);

    const int zero_elems = NN * D / 4 + NN / 4;
    zero_kernel<<<(zero_elems + 255) / 256, 256>>>();

    scatter_kernel<<<(n_edges * 32 + 255) / 256, 256>>>(h, src32, dst32, n_edges);

    sage_gemm_kernel<<<(n_nodes + 63) / 64, 256, smem_bytes>>>(
        h, Wself, Wneigh, bias, out, n_nodes);
}

// round 2
// speedup vs baseline: 2.7453x; 2.7453x over previous
#include <cuda_runtime.h>
#include <cstdint>

#define NN 100000
#define NE 1600000
#define D 128

// Scratch (no allocations allowed)
__device__ float g_neigh[(size_t)NN * D];   // segment sums
__device__ float g_deg[NN];                 // degrees
__device__ float g_wt[256 * 128];           // stacked transposed weights: [k 0..255][j 0..127]
__device__ int   g_fmt;                     // 1 = int32 indices, 0 = int64

// ---------------------------------------------------------------------------
// Detect whether src/dst are int32 or int64 (JAX default disables x64).
// int64 little-endian: odd 32-bit words are zero high-words (values < 1e5).
// ---------------------------------------------------------------------------
__global__ void detect_fmt_kernel(const int* __restrict__ src32) {
    __shared__ int flag;
    if (threadIdx.x == 0) flag = 0;
    __syncthreads();
    if (src32[2 * threadIdx.x + 1] != 0) atomicOr(&flag, 1);
    __syncthreads();
    if (threadIdx.x == 0) g_fmt = flag ? 1 : 0;
}

// ---------------------------------------------------------------------------
// Zero scratch + build transposed stacked weight matrix g_wt[k][j]:
//   k <  128 : Ws[j][k]
//   k >= 128 : Wn[j][k-128]
// ---------------------------------------------------------------------------
__global__ void prep_kernel(const float* __restrict__ Wself,
                            const float* __restrict__ Wneigh) {
    const int NV = NN * D / 4;       // float4 count for neigh
    const int ND = NN / 4;           // float4 count for deg
    int idx = blockIdx.x * blockDim.x + threadIdx.x;
    float4 z = make_float4(0.f, 0.f, 0.f, 0.f);
    if (idx < NV) {
        reinterpret_cast<float4*>(g_neigh)[idx] = z;
    } else if (idx < NV + ND) {
        reinterpret_cast<float4*>(g_deg)[idx - NV] = z;
    } else if (idx < NV + ND + 256 * 128) {
        int t = idx - (NV + ND);
        int k = t >> 7, j = t & 127;
        g_wt[t] = (k < 128) ? Wself[j * 128 + k] : Wneigh[j * 128 + (k - 128)];
    }
}

// ---------------------------------------------------------------------------
// Edge scatter: one warp per edge, vector reductions into L2-resident scratch.
// ---------------------------------------------------------------------------
__global__ void __launch_bounds__(256) scatter_kernel(
    const float* __restrict__ h,
    const int* __restrict__ src32,
    const int* __restrict__ dst32,
    int n_edges)
{
    int gw = (blockIdx.x * 256 + threadIdx.x) >> 5;
    if (gw >= n_edges) return;
    int lane = threadIdx.x & 31;

    int s, d;
    if (g_fmt) { s = src32[gw];     d = dst32[gw];     }
    else       { s = src32[2 * gw]; d = dst32[2 * gw]; }

    float4 v = reinterpret_cast<const float4*>(h + (size_t)s * D)[lane];
    float* p = g_neigh + (size_t)d * D + lane * 4;
    asm volatile("red.global.add.v4.f32 [%0], {%1, %2, %3, %4};"
                 :: "l"(p), "f"(v.x), "f"(v.y), "f"(v.z), "f"(v.w)
                 : "memory");
    if (lane == 0) atomicAdd(&g_deg[d], 1.0f);
}

// ---------------------------------------------------------------------------
// GEMM: out[n][j] = sum_k X[n][k] * g_wt[k][j] + b[j],  X = [h | neigh*invd]
// BM=128, BN=128, BK=16, 256 threads, 8x8 micro-tile per thread.
// As stored k-major [BK][132] (pad -> conflict-free), Bs [BK][132].
// fp32 accumulation with packed fma.rn.f32x2 (full-rate fp32 on sm_103a).
// ---------------------------------------------------------------------------
__device__ __forceinline__ unsigned long long fma2(
    unsigned long long a, unsigned long long b, unsigned long long c)
{
    unsigned long long d;
    asm("fma.rn.f32x2 %0, %1, %2, %3;" : "=l"(d) : "l"(a), "l"(b), "l"(c));
    return d;
}

__device__ __forceinline__ unsigned long long dup_f32(float a) {
    unsigned long long d;
    asm("mov.b64 %0, {%1, %1};" : "=l"(d) : "f"(a));
    return d;
}

#define APITCH 132

__global__ void __launch_bounds__(256, 2) sage_gemm_kernel(
    const float* __restrict__ h,
    const float* __restrict__ bias,
    float* __restrict__ out,
    int n_nodes)
{
    __shared__ float As[16 * APITCH];   // [k][row]
    __shared__ float Bs[16 * APITCH];   // [k][col]
    __shared__ float sinv[128];

    const int tid = threadIdx.x;
    const int nodeBase = blockIdx.x * 128;
    const int tx = tid & 15;            // col group
    const int ty = tid >> 4;            // row group
    const int row0 = ty * 8;
    const int col0 = tx * 8;

    // per-row inverse degree
    if (tid < 128) {
        int node = nodeBase + tid;
        sinv[tid] = (node < n_nodes) ? (1.0f / fmaxf(g_deg[node], 1.0f)) : 0.0f;
    }

    unsigned long long acc[8][4];
    #pragma unroll
    for (int i = 0; i < 8; i++)
        #pragma unroll
        for (int q = 0; q < 4; q++) acc[i][q] = 0ull;

    // staging indices
    const int lr = tid >> 2;            // 0..63 (row base for A staging)
    const int lk4 = tid & 3;            // which float4 along k
    __syncthreads();

    for (int kt = 0; kt < 16; kt++) {
        const int kbase = kt * 16;
        const bool neighPart = (kbase >= 128);
        const float* Xsrc = neighPart ? g_neigh : h;
        const int ksrc = neighPart ? (kbase - 128) : kbase;

        // Stage As: 128 rows x 16 k, k-major in smem
        #pragma unroll
        for (int rep = 0; rep < 2; rep++) {
            int row = lr + rep * 64;
            int node = nodeBase + row;
            float4 v = make_float4(0.f, 0.f, 0.f, 0.f);
            if (node < n_nodes)
                v = *reinterpret_cast<const float4*>(Xsrc + (size_t)node * D + ksrc + lk4 * 4);
            if (neighPart) {
                float sc = sinv[row];
                v.x *= sc; v.y *= sc; v.z *= sc; v.w *= sc;
            }
            As[(lk4 * 4 + 0) * APITCH + row] = v.x;
            As[(lk4 * 4 + 1) * APITCH + row] = v.y;
            As[(lk4 * 4 + 2) * APITCH + row] = v.z;
            As[(lk4 * 4 + 3) * APITCH + row] = v.w;
        }

        // Stage Bs: 16 k x 128 cols (coalesced from pre-transposed g_wt)
        #pragma unroll
        for (int rep = 0; rep < 2; rep++) {
            int f4 = tid + rep * 256;            // 0..511
            int kr = f4 >> 5;                    // 0..15
            int c4 = f4 & 31;                    // 0..31
            float4 w = *reinterpret_cast<const float4*>(g_wt + (kbase + kr) * 128 + c4 * 4);
            *reinterpret_cast<float4*>(Bs + kr * APITCH + c4 * 4) = w;
        }
        __syncthreads();

        #pragma unroll
        for (int kr = 0; kr < 16; kr++) {
            float4 a0 = *reinterpret_cast<const float4*>(As + kr * APITCH + row0);
            float4 a1 = *reinterpret_cast<const float4*>(As + kr * APITCH + row0 + 4);
            ulonglong2 b0 = *reinterpret_cast<const ulonglong2*>(Bs + kr * APITCH + col0);
            ulonglong2 b1 = *reinterpret_cast<const ulonglong2*>(Bs + kr * APITCH + col0 + 4);

            float av[8] = {a0.x, a0.y, a0.z, a0.w, a1.x, a1.y, a1.z, a1.w};
            #pragma unroll
            for (int i = 0; i < 8; i++) {
                unsigned long long ai = dup_f32(av[i]);
                acc[i][0] = fma2(ai, b0.x, acc[i][0]);
                acc[i][1] = fma2(ai, b0.y, acc[i][1]);
                acc[i][2] = fma2(ai, b1.x, acc[i][2]);
                acc[i][3] = fma2(ai, b1.y, acc[i][3]);
            }
        }
        __syncthreads();
    }

    // bias + store
    ulonglong2 bb0 = *reinterpret_cast<const ulonglong2*>(bias + col0);
    ulonglong2 bb1 = *reinterpret_cast<const ulonglong2*>(bias + col0 + 4);
    const unsigned long long one2 = dup_f32(1.0f);

    #pragma unroll
    for (int i = 0; i < 8; i++) {
        int node = nodeBase + row0 + i;
        if (node < n_nodes) {
            ulonglong2 o0, o1;
            o0.x = fma2(acc[i][0], one2, bb0.x);
            o0.y = fma2(acc[i][1], one2, bb0.y);
            o1.x = fma2(acc[i][2], one2, bb1.x);
            o1.y = fma2(acc[i][3], one2, bb1.y);
            *reinterpret_cast<ulonglong2*>(out + (size_t)node * D + col0) = o0;
            *reinterpret_cast<ulonglong2*>(out + (size_t)node * D + col0 + 4) = o1;
        }
    }
}

// ---------------------------------------------------------------------------
extern "C" void kernel_launch(void* const* d_in, const int* in_sizes, int n_in,
                              void* d_out, int out_size)
{
    const float* h      = (const float*)d_in[0];
    const int*   src32  = (const int*)d_in[1];
    const int*   dst32  = (const int*)d_in[2];
    const float* Wself  = (const float*)d_in[3];
    const float* Wneigh = (const float*)d_in[4];
    const float* bias   = (const float*)d_in[5];
    float*       out    = (float*)d_out;

    const int n_nodes = in_sizes[0] / D;   // 100000
    const int n_edges = in_sizes[1];       // 1600000 (element count, dtype-independent)

    detect_fmt_kernel<<<1, 256>>>(src32);

    const int prep_elems = NN * D / 4 + NN / 4 + 256 * 128;
    prep_kernel<<<(prep_elems + 255) / 256, 256>>>(Wself, Wneigh);

    scatter_kernel<<<(n_edges * 32 + 255) / 256, 256>>>(h, src32, dst32, n_edges);

    sage_gemm_kernel<<<(n_nodes + 127) / 128, 256>>>(h, bias, out, n_nodes);
}